// round 9
// baseline (speedup 1.0000x reference)
#include <cuda_runtime.h>
#include <math.h>

#define B_      512
#define NOBJ    3
#define FEATIN  2048
#define FEATSZ  512
#define EMB     512
#define HID     512
#define VOC     4096
#define MAXLEN  40
#define TSTEPS  38
#define SOS_IDX 1
#define EOS_IDX 2
#define FTDIM   (NOBJ*(FEATSZ+1))          /* 1539 */
#define LANGN   ((long long)B_*MAXLEN*VOC) /* 83,886,080 */
#define NVT     32                          /* vocab tiles of 128 */
#define NB      440                         /* persistent grid (<=444 slots @3/SM) */
#define NS      32                          /* 512 / 16 k-stages */
#define NLOG    256                         /* logits tiles per step */
#define NGH     192                         /* gh tiles per step */

// ---------------- device scratch (no allocations allowed) ----------------
__device__ float g_EW[VOC*3*HID];     // emb_W @ Wih^T : [4096,1536]
__device__ float g_fe[B_*NOBJ*FEATSZ];
__device__ float g_ft[B_*FTDIM];
__device__ float g_h[2][B_*HID];
__device__ float g_ht[B_*HID];        // hout transposed [512 u][512 row]
__device__ float g_gh[B_*3*HID];
__device__ float g_Wot[HID*VOC];      // out_W^T : [512][4096]
__device__ float g_Whht[HID*3*HID];   // Whh^T   : [512][1536]
__device__ float g_pm[B_*NVT];
__device__ float g_pse[B_*NVT];
__device__ int   g_pa[B_*NVT];
__device__ int   g_done[B_];
__device__ int   g_len[B_];
__device__ unsigned g_bcnt;
__device__ volatile unsigned g_bgen;
__device__ unsigned g_task;           // dynamic tile queue (reset each launch)

typedef unsigned long long u64;

__device__ __forceinline__ u64 pk2(float x, float y){ u64 r; asm("mov.b64 %0,{%1,%2};":"=l"(r):"f"(x),"f"(y)); return r; }
__device__ __forceinline__ u64 dup2(float x){ u64 r; asm("mov.b64 %0,{%1,%1};":"=l"(r):"f"(x)); return r; }
__device__ __forceinline__ u64 f2fma(u64 a,u64 b,u64 c){ u64 d; asm("fma.rn.f32x2 %0,%1,%2,%3;":"=l"(d):"l"(a),"l"(b),"l"(c)); return d; }
__device__ __forceinline__ float2 up2(u64 v){ float lo,hi; asm("mov.b64 {%0,%1},%2;":"=f"(lo),"=f"(hi):"l"(v)); float2 f; f.x=lo; f.y=hi; return f; }

__device__ __forceinline__ unsigned su32(const void* p){ return (unsigned)__cvta_generic_to_shared(p); }
__device__ __forceinline__ void cpa16(unsigned dst, const float* src){
    asm volatile("cp.async.cg.shared.global [%0], [%1], 16;" :: "r"(dst), "l"(src) : "memory");
}
__device__ __forceinline__ void cpcommit(){ asm volatile("cp.async.commit_group;" ::: "memory"); }
__device__ __forceinline__ void pfL2(const float* p){
    asm volatile("prefetch.global.L2 [%0];" :: "l"(p));
}

// ---------------- shared memory ------------------------------------------
struct SmemU {
    union {
        struct { float As[3][16][68]; float Ws[3][16][132]; } x3;     // 38400 B
        struct { float As[16][68];    float Ws[16][132];    } x;      // prologue
        struct { float m[64][16]; int a[64][16]; float rm[64]; } red;
        struct { float T[32][33]; } tr;
        struct { float sp[2]; int pred[2]; } y;
    };
    int task;                                                          // dispatch slot
};
#define AS_STRIDE 4352u   /* 16*68*4 */
#define WS_STRIDE 8448u   /* 16*132*4 */

// ---------------- grid-wide barrier ---------------------------------------
__device__ __forceinline__ void gridbar()
{
    __threadfence();
    __syncthreads();
    if (threadIdx.x == 0) {
        const unsigned my = g_bgen;
        const unsigned t = atomicAdd(&g_bcnt, 1u);
        if (t == (unsigned)(NB - 1)) {
            g_bcnt = 0u;
            __threadfence();
            g_bgen = my + 1u;
        } else {
            while (g_bgen == my) { }
            __threadfence();
        }
    }
    __syncthreads();
}

// ---------------- prologue 64x64 GEMM tile (single-buffered, one-time) ----
__device__ void gemm64_tile(const float* __restrict__ A, int lda,
                            const float* __restrict__ W, int ldw,
                            const float* __restrict__ bias,
                            float* __restrict__ C, int ldc, int K,
                            int bm, int bn, SmemU* sm)
{
    float (*As)[68]  = sm->x.As;
    float (*Ws)[132] = sm->x.Ws;
    const int tid = threadIdx.x;
    const int tx = tid & 15, ty = tid >> 4;
    const int lk = tid & 15;
    const int lm = (tid >> 4) << 2;

    u64 acc[4][2];
#pragma unroll
    for (int i = 0; i < 4; i++) { acc[i][0] = 0ULL; acc[i][1] = 0ULL; }

    __syncthreads();
    for (int kt = 0; kt < K; kt += 16) {
        const bool ok = (kt + lk) < K;
#pragma unroll
        for (int i = 0; i < 4; i++) {
            const int m = lm + i;
            As[lk][m] = ok ? A[(size_t)(bm + m) * lda + kt + lk] : 0.f;
            Ws[lk][m] = ok ? W[(size_t)(bn + m) * ldw + kt + lk] : 0.f;
        }
        __syncthreads();
#pragma unroll
        for (int k = 0; k < 16; k++) {
            float4 a4 = *(const float4*)&As[k][ty << 2];
            float4 b4 = *(const float4*)&Ws[k][tx << 2];
            u64 b01 = pk2(b4.x, b4.y), b23 = pk2(b4.z, b4.w);
            u64 a0 = dup2(a4.x), a1 = dup2(a4.y), a2 = dup2(a4.z), a3 = dup2(a4.w);
            acc[0][0] = f2fma(a0, b01, acc[0][0]); acc[0][1] = f2fma(a0, b23, acc[0][1]);
            acc[1][0] = f2fma(a1, b01, acc[1][0]); acc[1][1] = f2fma(a1, b23, acc[1][1]);
            acc[2][0] = f2fma(a2, b01, acc[2][0]); acc[2][1] = f2fma(a2, b23, acc[2][1]);
            acc[3][0] = f2fma(a3, b01, acc[3][0]); acc[3][1] = f2fma(a3, b23, acc[3][1]);
        }
        __syncthreads();
    }
    const int n0 = bn + (tx << 2);
    float bb0 = 0.f, bb1 = 0.f, bb2 = 0.f, bb3 = 0.f;
    if (bias) { bb0 = bias[n0]; bb1 = bias[n0+1]; bb2 = bias[n0+2]; bb3 = bias[n0+3]; }
#pragma unroll
    for (int r = 0; r < 4; r++) {
        float2 c0 = up2(acc[r][0]), c1 = up2(acc[r][1]);
        float* cp = C + (size_t)(bm + (ty << 2) + r) * ldc + n0;
        cp[0] = c0.x + bb0; cp[1] = c0.y + bb1; cp[2] = c1.x + bb2; cp[3] = c1.y + bb3;
    }
}

// ---------------- tiled transpose: src[rows][cols] -> dst[cols][rows] -----
__device__ void transpose_tiles(const float* __restrict__ src, float* __restrict__ dst,
                                int rows, int cols, SmemU* sm)
{
    const int tid = threadIdx.x;
    const int lane = tid & 31, r8 = tid >> 5;
    const int tcols = cols >> 5, trows = rows >> 5;
    for (int j = blockIdx.x; j < trows * tcols; j += NB) {
        const int tr_ = j / tcols, tc = j % tcols;
        const int r0 = tr_ << 5, c0 = tc << 5;
        __syncthreads();
#pragma unroll
        for (int i = 0; i < 4; i++) {
            const int r = (i << 3) + r8;
            sm->tr.T[r][lane] = src[(size_t)(r0 + r) * cols + c0 + lane];
        }
        __syncthreads();
#pragma unroll
        for (int i = 0; i < 4; i++) {
            const int r = (i << 3) + r8;
            dst[(size_t)(c0 + r) * rows + r0 + lane] = sm->tr.T[lane][r];
        }
    }
    __syncthreads();
}

// ---------------- logits tile (cp.async 3-stage) + fused reduce -----------
__device__ void logits_tile(int ti, const float* __restrict__ Ht,
                            const float* __restrict__ OWt,
                            const float* __restrict__ ob,
                            const float* __restrict__ gum, SmemU* sm)
{
    const int vt = ti & 31;
    const int bm = (ti >> 5) << 6;
    const int bn = vt << 7;
    const int tid = threadIdx.x, tx = tid & 15, ty = tid >> 4;

    // L2 prefetch of this tile's gumbel block (64 rows x 512 B = 256 lines)
    pfL2(gum + (size_t)(bm + (tid >> 2)) * VOC + bn + ((tid & 3) << 5));

    const int ka  = tid >> 4,          m4  = (tid & 15) << 2;
    const int kw0 = tid >> 5,          n40 = (tid & 31) << 2;
    const int kw1 = (tid + 256) >> 5,  n41 = (tid & 31) << 2;
    const float* srcA  = Ht  + (size_t)ka  * 512  + bm + m4;
    const float* srcW0 = OWt + (size_t)kw0 * 4096 + bn + n40;
    const float* srcW1 = OWt + (size_t)kw1 * 4096 + bn + n41;
    const unsigned dstA  = su32(&sm->x3.As[0][ka][m4]);
    const unsigned dstW0 = su32(&sm->x3.Ws[0][kw0][n40]);
    const unsigned dstW1 = su32(&sm->x3.Ws[0][kw1][n41]);

    u64 acc[4][4];
#pragma unroll
    for (int i = 0; i < 4; i++)
#pragma unroll
        for (int j = 0; j < 4; j++) acc[i][j] = 0ULL;

    auto issue = [&](int s, int b) {
        const size_t ko = (size_t)s << 4;
        cpa16(dstA  + (unsigned)b * AS_STRIDE, srcA  + ko * 512);
        cpa16(dstW0 + (unsigned)b * WS_STRIDE, srcW0 + ko * 4096);
        cpa16(dstW1 + (unsigned)b * WS_STRIDE, srcW1 + ko * 4096);
        cpcommit();
    };
    issue(0, 0);
    issue(1, 1);

    for (int s = 0; s < NS; s++) {
        if (s < NS - 1) asm volatile("cp.async.wait_group 1;" ::: "memory");
        else            asm volatile("cp.async.wait_group 0;" ::: "memory");
        __syncthreads();
        if (s + 2 < NS) issue(s + 2, (s + 2) % 3);
        const int cb = s % 3;
#pragma unroll
        for (int k = 0; k < 16; k++) {
            float4 a4  = *(const float4*)&sm->x3.As[cb][k][ty << 2];
            float4 b4a = *(const float4*)&sm->x3.Ws[cb][k][tx << 3];
            float4 b4b = *(const float4*)&sm->x3.Ws[cb][k][(tx << 3) + 4];
            u64 b0 = pk2(b4a.x, b4a.y), b1 = pk2(b4a.z, b4a.w);
            u64 b2 = pk2(b4b.x, b4b.y), b3 = pk2(b4b.z, b4b.w);
            u64 a0 = dup2(a4.x), a1 = dup2(a4.y), a2 = dup2(a4.z), a3 = dup2(a4.w);
            acc[0][0]=f2fma(a0,b0,acc[0][0]); acc[0][1]=f2fma(a0,b1,acc[0][1]); acc[0][2]=f2fma(a0,b2,acc[0][2]); acc[0][3]=f2fma(a0,b3,acc[0][3]);
            acc[1][0]=f2fma(a1,b0,acc[1][0]); acc[1][1]=f2fma(a1,b1,acc[1][1]); acc[1][2]=f2fma(a1,b2,acc[1][2]); acc[1][3]=f2fma(a1,b3,acc[1][3]);
            acc[2][0]=f2fma(a2,b0,acc[2][0]); acc[2][1]=f2fma(a2,b1,acc[2][1]); acc[2][2]=f2fma(a2,b2,acc[2][2]); acc[2][3]=f2fma(a2,b3,acc[2][3]);
            acc[3][0]=f2fma(a3,b0,acc[3][0]); acc[3][1]=f2fma(a3,b1,acc[3][1]); acc[3][2]=f2fma(a3,b2,acc[3][2]); acc[3][3]=f2fma(a3,b3,acc[3][3]);
        }
    }
    __syncthreads();   // compute done before red union reuse

    float (*s_m)[16] = sm->red.m;
    int   (*s_a)[16] = sm->red.a;
    float* s_rm = sm->red.rm;

    const int row0 = ty << 2;
    const int c0 = tx << 3;
    float z[4][8];
#pragma unroll
    for (int r = 0; r < 4; r++) {
        const float* gp = gum + (size_t)(bm + row0 + r) * VOC + bn + c0;
        float4 g0 = *(const float4*)&gp[0];
        float4 g1 = *(const float4*)&gp[4];
        float4 o0 = *(const float4*)&ob[bn + c0];
        float4 o1 = *(const float4*)&ob[bn + c0 + 4];
        float2 d0 = up2(acc[r][0]), d1 = up2(acc[r][1]), d2 = up2(acc[r][2]), d3 = up2(acc[r][3]);
        z[r][0] = d0.x + o0.x + g0.x; z[r][1] = d0.y + o0.y + g0.y;
        z[r][2] = d1.x + o0.z + g0.z; z[r][3] = d1.y + o0.w + g0.w;
        z[r][4] = d2.x + o1.x + g1.x; z[r][5] = d2.y + o1.y + g1.y;
        z[r][6] = d3.x + o1.z + g1.z; z[r][7] = d3.y + o1.w + g1.w;
    }
#pragma unroll
    for (int r = 0; r < 4; r++) {
        float m = -__int_as_float(0x7f800000); int a = bn + c0;
#pragma unroll
        for (int j = 0; j < 8; j++)
            if (z[r][j] > m) { m = z[r][j]; a = bn + c0 + j; }
        s_m[row0 + r][tx] = m; s_a[row0 + r][tx] = a;
    }
    __syncthreads();
    if (tid < 64) {
        float m = s_m[tid][0]; int a = s_a[tid][0];
#pragma unroll
        for (int x = 1; x < 16; x++)
            if (s_m[tid][x] > m) { m = s_m[tid][x]; a = s_a[tid][x]; }
        s_rm[tid] = m; s_a[tid][0] = a;
    }
    __syncthreads();
#pragma unroll
    for (int r = 0; r < 4; r++) {
        const float rm = s_rm[row0 + r];
        float se = 0.f;
#pragma unroll
        for (int j = 0; j < 8; j++) se += __expf(z[r][j] - rm);
        s_m[row0 + r][tx] = se;
    }
    __syncthreads();
    if (tid < 64) {
        float se = 0.f;
#pragma unroll
        for (int x = 0; x < 16; x++) se += s_m[tid][x];
        const int b = bm + tid;
        g_pm[b * NVT + vt]  = s_rm[tid];
        g_pa[b * NVT + vt]  = s_a[tid][0];
        g_pse[b * NVT + vt] = se;
    }
}

// ---------------- gh tile (cp.async 3-stage), 64x64 -----------------------
__device__ void gh_tile(int j, const float* __restrict__ Ht,
                        const float* __restrict__ Wt,   // g_Whht [512][1536]
                        const float* __restrict__ bias, SmemU* sm)
{
    const int bm = (j / 24) << 6;
    const int bn = (j % 24) << 6;
    const int tid = threadIdx.x, tx = tid & 15, ty = tid >> 4;

    const int ka = tid >> 4, m4 = (tid & 15) << 2;
    const float* srcA = Ht + (size_t)ka * 512  + bm + m4;
    const float* srcW = Wt + (size_t)ka * 1536 + bn + m4;
    const unsigned dstA = su32(&sm->x3.As[0][ka][m4]);
    const unsigned dstW = su32(&sm->x3.Ws[0][ka][m4]);

    u64 acc[4][2];
#pragma unroll
    for (int i = 0; i < 4; i++) { acc[i][0] = 0ULL; acc[i][1] = 0ULL; }

    auto issue = [&](int s, int b) {
        const size_t ko = (size_t)s << 4;
        cpa16(dstA + (unsigned)b * AS_STRIDE, srcA + ko * 512);
        cpa16(dstW + (unsigned)b * WS_STRIDE, srcW + ko * 1536);
        cpcommit();
    };
    issue(0, 0);
    issue(1, 1);

    for (int s = 0; s < NS; s++) {
        if (s < NS - 1) asm volatile("cp.async.wait_group 1;" ::: "memory");
        else            asm volatile("cp.async.wait_group 0;" ::: "memory");
        __syncthreads();
        if (s + 2 < NS) issue(s + 2, (s + 2) % 3);
        const int cb = s % 3;
#pragma unroll
        for (int k = 0; k < 16; k++) {
            float4 a4 = *(const float4*)&sm->x3.As[cb][k][ty << 2];
            float4 b4 = *(const float4*)&sm->x3.Ws[cb][k][tx << 2];
            u64 b01 = pk2(b4.x, b4.y), b23 = pk2(b4.z, b4.w);
            u64 a0 = dup2(a4.x), a1 = dup2(a4.y), a2 = dup2(a4.z), a3 = dup2(a4.w);
            acc[0][0] = f2fma(a0, b01, acc[0][0]); acc[0][1] = f2fma(a0, b23, acc[0][1]);
            acc[1][0] = f2fma(a1, b01, acc[1][0]); acc[1][1] = f2fma(a1, b23, acc[1][1]);
            acc[2][0] = f2fma(a2, b01, acc[2][0]); acc[2][1] = f2fma(a2, b23, acc[2][1]);
            acc[3][0] = f2fma(a3, b01, acc[3][0]); acc[3][1] = f2fma(a3, b23, acc[3][1]);
        }
    }
    const int n0 = bn + (tx << 2);
    const float bb0 = bias[n0], bb1 = bias[n0+1], bb2 = bias[n0+2], bb3 = bias[n0+3];
#pragma unroll
    for (int r = 0; r < 4; r++) {
        float2 c0 = up2(acc[r][0]), c1 = up2(acc[r][1]);
        float* cp = g_gh + (size_t)(bm + (ty << 2) + r) * 1536 + n0;
        cp[0] = c0.x + bb0; cp[1] = c0.y + bb1; cp[2] = c1.x + bb2; cp[3] = c1.y + bb3;
    }
}

// ---------------- Y phase: warp-parallel combine + GRU --------------------
__device__ void phase_Y(int t, const float* __restrict__ hin, float* __restrict__ hout,
                        const float* __restrict__ bih, float* __restrict__ lang, SmemU* sm)
{
    const int row0 = blockIdx.x << 1;
    const int tid = threadIdx.x;
    const int wid = tid >> 5, lane = tid & 31;

    if (wid < 2) {
        const int row = row0 + wid;
        int A; float spv;
        if (t > 0) {
            float m = g_pm[row * NVT + lane];
            int   a = g_pa[row * NVT + lane];
            float s = g_pse[row * NVT + lane];
#pragma unroll
            for (int off = 16; off > 0; off >>= 1) {
                const float m2 = __shfl_xor_sync(0xffffffffu, m, off);
                const int   a2 = __shfl_xor_sync(0xffffffffu, a, off);
                const float s2 = __shfl_xor_sync(0xffffffffu, s, off);
                const float M = fmaxf(m, m2);
                s = s * __expf(m - M) + s2 * __expf(m2 - M);
                if (m2 > m || (m2 == m && a2 < a)) a = a2;
                m = M;
            }
            A = a;
            const float si = 1.0f / s;
            spv = (1.0f + si) - si;
            if (lane == 0 && !g_done[row]) {
                lang[(size_t)row * MAXLEN * VOC + (size_t)t * VOC + A] = spv;
                g_len[row] += 1;
                if (A == EOS_IDX) g_done[row] = 1;
            }
        } else { A = SOS_IDX; spv = 1.0f; }
        if (lane == 0) { sm->y.pred[wid] = A; sm->y.sp[wid] = spv; }
    }
    __syncthreads();
    const int p0 = sm->y.pred[0], p1 = sm->y.pred[1];
    const float sp0 = sm->y.sp[0], sp1 = sm->y.sp[1];

#pragma unroll
    for (int j = 0; j < 4; j++) {
        const int idx = j * 256 + tid;          // 0..1023
        const int rr_ = idx >> 9;               // 0 or 1
        const int u = idx & 511;
        const int row = row0 + rr_;
        const int p = rr_ ? p1 : p0;
        const float spv = rr_ ? sp1 : sp0;
        const float* ew = g_EW + (size_t)p * 1536;
        const float* gh = g_gh + (size_t)row * 1536;
        const float gir = fmaf(spv, ew[u],        bih[u]);
        const float giz = fmaf(spv, ew[u + 512],  bih[u + 512]);
        const float gin = fmaf(spv, ew[u + 1024], bih[u + 1024]);
        const float r = 1.0f / (1.0f + expf(-(gir + gh[u])));
        const float zz = 1.0f / (1.0f + expf(-(giz + gh[u + 512])));
        const float n = tanhf(gin + r * gh[u + 1024]);
        const float hv = (1.0f - zz) * n + zz * hin[(size_t)row * HID + u];
        hout[(size_t)row * HID + u] = hv;
        g_ht[(size_t)u * 512 + row] = hv;        // transposed copy for GEMMs
    }
}

// ---------------- the single persistent kernel -----------------------------
__global__ __launch_bounds__(256, 3) void speaker_all(
    const float* __restrict__ feats, const int* __restrict__ targets,
    const float* __restrict__ feat_W, const float* __restrict__ feat_b,
    const float* __restrict__ emb_W, const float* __restrict__ init_W,
    const float* __restrict__ init_b, const float* __restrict__ Wih,
    const float* __restrict__ Whh, const float* __restrict__ bih,
    const float* __restrict__ bhh, const float* __restrict__ out_W,
    const float* __restrict__ out_b, const float* __restrict__ gumbel,
    float* __restrict__ out, long long n)
{
    __shared__ SmemU sm;
    const int blk = blockIdx.x;
    const int tid = threadIdx.x;
    float* h0 = g_h[0];
    float* h1 = g_h[1];

    // ---- P0: reset task queue; zero output; fe GEMM; EW GEMM; transposes ----
    if (blk == 0 && tid == 0) g_task = 0u;   // replay determinism
    {
        const long long n4 = n >> 2;
        float4 zv; zv.x = zv.y = zv.z = zv.w = 0.f;
        for (long long i = (long long)blk * 256 + tid; i < n4; i += (long long)NB * 256)
            ((float4*)out)[i] = zv;
        if (blk == 0 && tid < (int)(n & 3)) out[(n & ~3LL) + tid] = 0.f;
    }
    if (blk < 192)   // fe = feats @ feat_W^T + feat_b : [1536, 512]
        gemm64_tile(feats, FEATIN, feat_W, FEATIN, feat_b,
                    g_fe, FEATSZ, FEATIN, (blk >> 3) << 6, (blk & 7) << 6, &sm);
    for (int j = blk; j < 1536; j += NB)   // EW = emb_W @ Wih^T : [4096, 1536]
        gemm64_tile(emb_W, EMB, Wih, EMB, (const float*)0,
                    g_EW, 3 * HID, EMB, (j / 24) << 6, (j % 24) << 6, &sm);
    transpose_tiles(out_W, g_Wot, VOC, HID, &sm);     // [4096,512] -> [512,4096]
    transpose_tiles(Whh, g_Whht, 3 * HID, HID, &sm);  // [1536,512] -> [512,1536]
    gridbar();

    // ---- P1: build ft; init per-row state + SOS ----
    for (int idx = blk * 256 + tid; idx < B_ * FTDIM; idx += NB * 256) {
        const int b = idx / FTDIM, c = idx % FTDIM;
        const int o = c / (FEATSZ + 1), jj = c % (FEATSZ + 1);
        g_ft[idx] = (jj < FEATSZ) ? g_fe[((size_t)b * NOBJ + o) * FEATSZ + jj]
                                  : ((targets[b] == o) ? 1.f : 0.f);
    }
    if (blk < 2) {
        const int b = blk * 256 + tid;
        g_done[b] = 0; g_len[b] = 1;
        out[(size_t)b * MAXLEN * VOC + SOS_IDX] = 1.0f;
    }
    gridbar();

    // ---- P2: h0 = ft @ init_W^T + init_b : [512, 512], K=1539 ----
    if (blk < 64)
        gemm64_tile(g_ft, FTDIM, init_W, FTDIM, init_b,
                    h0, HID, FTDIM, (blk >> 3) << 6, (blk & 7) << 6, &sm);
    gridbar();

    // ---- P3: gh(0) = h0 @ Whh^T + bhh ----
    if (blk < 192)
        gemm64_tile(h0, HID, Whh, HID, bhh,
                    g_gh, 3 * HID, HID, (blk / 24) << 6, (blk % 24) << 6, &sm);
    gridbar();

    // ---- main loop: 2 barriers per step; X phase is a dynamic tile queue ----
    unsigned taskbase = 0u;
    for (int t = 0; t < TSTEPS; t++) {
        const float* hin = (t & 1) ? h1 : h0;
        float* hout      = (t & 1) ? h0 : h1;

        if (blk < 256) phase_Y(t, hin, hout, bih, out, &sm);
        gridbar();

        const int ntasks = (t < TSTEPS - 1) ? (NLOG + NGH) : NLOG;
        const float* gum = gumbel + (size_t)t * B_ * VOC;
        for (;;) {
            __syncthreads();                           // smem reuse + task slot guard
            if (tid == 0) {
                const unsigned i = atomicAdd(&g_task, 1u);
                sm.task = (int)(i - taskbase);
            }
            __syncthreads();
            const int ti = sm.task;
            if (ti >= ntasks) break;
            if (ti < NLOG) logits_tile(ti, g_ht, g_Wot, out_b, gum, &sm);
            else           gh_tile(ti - NLOG, g_ht, g_Whht, bhh, &sm);
        }
        taskbase += (unsigned)(ntasks + NB);           // each block fails exactly one grab
        gridbar();
    }

    // ---- epilogue: combine(T-1) -> lang pos 38; finalize row outputs ----
    if (blk < 256) {
        const int wid = tid >> 5, lane = tid & 31;
        if (wid < 2) {
            const int row = (blk << 1) + wid;
            float m = g_pm[row * NVT + lane];
            int   a = g_pa[row * NVT + lane];
            float s = g_pse[row * NVT + lane];
#pragma unroll
            for (int off = 16; off > 0; off >>= 1) {
                const float m2 = __shfl_xor_sync(0xffffffffu, m, off);
                const int   a2 = __shfl_xor_sync(0xffffffffu, a, off);
                const float s2 = __shfl_xor_sync(0xffffffffu, s, off);
                const float M = fmaxf(m, m2);
                s = s * __expf(m - M) + s2 * __expf(m2 - M);
                if (m2 > m || (m2 == m && a2 < a)) a = a2;
                m = M;
            }
            if (lane == 0) {
                const float si = 1.0f / s;
                const float spv = (1.0f + si) - si;
                int L = g_len[row];
                int done = g_done[row];
                if (!done) {
                    out[(size_t)row * MAXLEN * VOC + (size_t)TSTEPS * VOC + a] = spv;
                    L += 1;
                    if (a == EOS_IDX) done = 1;
                }
                if (!done) {
                    out[(size_t)row * MAXLEN * VOC + (size_t)(MAXLEN - 1) * VOC + EOS_IDX] = 1.0f;
                    L += 1;
                }
                if (LANGN + row < n) out[LANGN + row] = (float)L;
            }
        }
    }
}

// ---------------------------------------------------------------------------
extern "C" void kernel_launch(void* const* d_in, const int* in_sizes, int n_in,
                              void* d_out, int out_size)
{
    const float* feats   = (const float*)d_in[0];
    const int*   targets = (const int*)  d_in[1];
    const float* feat_W  = (const float*)d_in[2];
    const float* feat_b  = (const float*)d_in[3];
    const float* emb_W   = (const float*)d_in[4];
    const float* init_W  = (const float*)d_in[5];
    const float* init_b  = (const float*)d_in[6];
    const float* Wih     = (const float*)d_in[7];
    const float* Whh     = (const float*)d_in[8];
    const float* bih     = (const float*)d_in[9];
    const float* bhh     = (const float*)d_in[10];
    const float* out_W   = (const float*)d_in[11];
    const float* out_b   = (const float*)d_in[12];
    const float* gumbel  = (const float*)d_in[13];

    speaker_all<<<NB, 256>>>(feats, targets, feat_W, feat_b, emb_W, init_W,
                             init_b, Wih, Whh, bih, bhh, out_W, out_b, gumbel,
                             (float*)d_out, (long long)out_size);
}

// round 10
// speedup vs baseline: 1.4542x; 1.4542x over previous
#include <cuda_runtime.h>
#include <math.h>

#define B_      512
#define NOBJ    3
#define FEATIN  2048
#define FEATSZ  512
#define EMB     512
#define HID     512
#define VOC     4096
#define MAXLEN  40
#define TSTEPS  38
#define SOS_IDX 1
#define EOS_IDX 2
#define FTDIM   (NOBJ*(FEATSZ+1))          /* 1539 */
#define LANGN   ((long long)B_*MAXLEN*VOC) /* 83,886,080 */
#define NVT     32                          /* vocab tiles of 128 */
#define NB      444                         /* persistent grid = 3 x 148 SM */
#define NT      128                         /* threads per block */
#define NS      32                          /* 512 / 16 k-stages */
#define NLOG    256                         /* logits tiles per step */
#define NGH     192                         /* gh tiles per step */

// ---------------- device scratch (no allocations allowed) ----------------
__device__ float g_EW[VOC*3*HID];     // emb_W @ Wih^T : [4096,1536]
__device__ float g_fe[B_*NOBJ*FEATSZ];
__device__ float g_ft[B_*FTDIM];
__device__ float g_h[2][B_*HID];
__device__ float g_ht[B_*HID];        // hout transposed [512 u][512 row]
__device__ float g_gh[B_*3*HID];
__device__ float g_Wot[HID*VOC];      // out_W^T : [512][4096]
__device__ float g_Whht[HID*3*HID];   // Whh^T   : [512][1536]
__device__ float g_pm[B_*NVT];
__device__ float g_pse[B_*NVT];
__device__ int   g_pa[B_*NVT];
__device__ int   g_done[B_];
__device__ int   g_len[B_];
__device__ unsigned g_bcnt;
__device__ volatile unsigned g_bgen;
__device__ unsigned g_task;

typedef unsigned long long u64;

__device__ __forceinline__ u64 pk2(float x, float y){ u64 r; asm("mov.b64 %0,{%1,%2};":"=l"(r):"f"(x),"f"(y)); return r; }
__device__ __forceinline__ u64 dup2(float x){ u64 r; asm("mov.b64 %0,{%1,%1};":"=l"(r):"f"(x)); return r; }
__device__ __forceinline__ u64 f2fma(u64 a,u64 b,u64 c){ u64 d; asm("fma.rn.f32x2 %0,%1,%2,%3;":"=l"(d):"l"(a),"l"(b),"l"(c)); return d; }
__device__ __forceinline__ float2 up2(u64 v){ float lo,hi; asm("mov.b64 {%0,%1},%2;":"=f"(lo),"=f"(hi):"l"(v)); float2 f; f.x=lo; f.y=hi; return f; }

__device__ __forceinline__ unsigned su32(const void* p){ return (unsigned)__cvta_generic_to_shared(p); }
__device__ __forceinline__ void cpa16(unsigned dst, const float* src){
    asm volatile("cp.async.cg.shared.global [%0], [%1], 16;" :: "r"(dst), "l"(src) : "memory");
}
__device__ __forceinline__ void cpcommit(){ asm volatile("cp.async.commit_group;" ::: "memory"); }
__device__ __forceinline__ void pfL2(const float* p){
    asm volatile("prefetch.global.L2 [%0];" :: "l"(p));
}

// ---------------- shared memory ------------------------------------------
struct SmemU {
    union {
        struct { float As[3][16][68]; float Ws[3][16][132]; } x3;     // 38400 B
        struct { float As[16][68];    float Ws[16][132];    } x;      // prologue
        struct { float m[64][16]; int a[64][16]; float rm[64]; } red;
        struct { float T[32][33]; } tr;
        struct { float sp[2]; int pred[2]; } y;
    };
    int task;
};
#define AS_STRIDE 4352u   /* 16*68*4  */
#define WS_STRIDE 8448u   /* 16*132*4 */
#define AS_ROW    272u    /* 68*4     */
#define WS_ROW    528u    /* 132*4    */

// ---------------- grid-wide barrier ---------------------------------------
__device__ __forceinline__ void gridbar()
{
    __threadfence();
    __syncthreads();
    if (threadIdx.x == 0) {
        const unsigned my = g_bgen;
        const unsigned t = atomicAdd(&g_bcnt, 1u);
        if (t == (unsigned)(NB - 1)) {
            g_bcnt = 0u;
            __threadfence();
            g_bgen = my + 1u;
        } else {
            while (g_bgen == my) { }
            __threadfence();
        }
    }
    __syncthreads();
}

// ---------------- prologue 64x64 GEMM tile (128 threads, 8m x 4n) ---------
__device__ void gemm64_tile(const float* __restrict__ A, int lda,
                            const float* __restrict__ W, int ldw,
                            const float* __restrict__ bias,
                            float* __restrict__ C, int ldc, int K,
                            int bm, int bn, SmemU* sm)
{
    float (*As)[68]  = sm->x.As;
    float (*Ws)[132] = sm->x.Ws;
    const int tid = threadIdx.x;
    const int tx = tid & 15, ty = tid >> 4;          // tx 0..15, ty 0..7
    const int ty8 = ty << 3;
    const int lk = tid & 15;
    const int lm0 = (tid >> 4) << 3;                 // 8 rows per thread

    u64 acc[8][2];
#pragma unroll
    for (int i = 0; i < 8; i++) { acc[i][0] = 0ULL; acc[i][1] = 0ULL; }

    __syncthreads();
    for (int kt = 0; kt < K; kt += 16) {
        const bool ok = (kt + lk) < K;
#pragma unroll
        for (int i = 0; i < 8; i++) {
            const int m = lm0 + i;
            As[lk][m] = ok ? A[(size_t)(bm + m) * lda + kt + lk] : 0.f;
            Ws[lk][m] = ok ? W[(size_t)(bn + m) * ldw + kt + lk] : 0.f;
        }
        __syncthreads();
#pragma unroll
        for (int k = 0; k < 16; k++) {
            float4 a0 = *(const float4*)&As[k][ty8];
            float4 a1 = *(const float4*)&As[k][ty8 + 4];
            float4 w0 = *(const float4*)&Ws[k][tx << 2];
            u64 b0 = pk2(w0.x, w0.y), b1 = pk2(w0.z, w0.w);
            u64 A0 = dup2(a0.x), A1 = dup2(a0.y), A2 = dup2(a0.z), A3 = dup2(a0.w);
            u64 A4 = dup2(a1.x), A5 = dup2(a1.y), A6 = dup2(a1.z), A7 = dup2(a1.w);
            acc[0][0]=f2fma(A0,b0,acc[0][0]); acc[0][1]=f2fma(A0,b1,acc[0][1]);
            acc[1][0]=f2fma(A1,b0,acc[1][0]); acc[1][1]=f2fma(A1,b1,acc[1][1]);
            acc[2][0]=f2fma(A2,b0,acc[2][0]); acc[2][1]=f2fma(A2,b1,acc[2][1]);
            acc[3][0]=f2fma(A3,b0,acc[3][0]); acc[3][1]=f2fma(A3,b1,acc[3][1]);
            acc[4][0]=f2fma(A4,b0,acc[4][0]); acc[4][1]=f2fma(A4,b1,acc[4][1]);
            acc[5][0]=f2fma(A5,b0,acc[5][0]); acc[5][1]=f2fma(A5,b1,acc[5][1]);
            acc[6][0]=f2fma(A6,b0,acc[6][0]); acc[6][1]=f2fma(A6,b1,acc[6][1]);
            acc[7][0]=f2fma(A7,b0,acc[7][0]); acc[7][1]=f2fma(A7,b1,acc[7][1]);
        }
        __syncthreads();
    }
    const int n0 = bn + (tx << 2);
    float bb0 = 0.f, bb1 = 0.f, bb2 = 0.f, bb3 = 0.f;
    if (bias) { bb0 = bias[n0]; bb1 = bias[n0+1]; bb2 = bias[n0+2]; bb3 = bias[n0+3]; }
#pragma unroll
    for (int r = 0; r < 8; r++) {
        float2 c0 = up2(acc[r][0]), c1 = up2(acc[r][1]);
        float* cp = C + (size_t)(bm + ty8 + r) * ldc + n0;
        cp[0] = c0.x + bb0; cp[1] = c0.y + bb1; cp[2] = c1.x + bb2; cp[3] = c1.y + bb3;
    }
}

// ---------------- tiled transpose (128 threads) ---------------------------
__device__ void transpose_tiles(const float* __restrict__ src, float* __restrict__ dst,
                                int rows, int cols, SmemU* sm)
{
    const int tid = threadIdx.x;
    const int lane = tid & 31, r4 = tid >> 5;        // r4 0..3
    const int tcols = cols >> 5, trows = rows >> 5;
    for (int j = blockIdx.x; j < trows * tcols; j += NB) {
        const int tr_ = j / tcols, tc = j % tcols;
        const int r0 = tr_ << 5, c0 = tc << 5;
        __syncthreads();
#pragma unroll
        for (int i = 0; i < 8; i++) {
            const int r = (i << 2) + r4;
            sm->tr.T[r][lane] = src[(size_t)(r0 + r) * cols + c0 + lane];
        }
        __syncthreads();
#pragma unroll
        for (int i = 0; i < 8; i++) {
            const int r = (i << 2) + r4;
            dst[(size_t)(c0 + r) * rows + r0 + lane] = sm->tr.T[lane][r];
        }
    }
    __syncthreads();
}

// ---------------- logits tile (cp.async, 8m x 8n per thread) --------------
__device__ void logits_tile(int ti, const float* __restrict__ Ht,
                            const float* __restrict__ OWt,
                            const float* __restrict__ ob,
                            const float* __restrict__ gum, SmemU* sm)
{
    const int vt = ti & 31;
    const int bm = (ti >> 5) << 6;
    const int bn = vt << 7;
    const int tid = threadIdx.x;
    const int tx = tid & 15, ty = tid >> 4;          // tx 0..15, ty 0..7
    const int ty8 = ty << 3, tx8 = tx << 3;

    // L2 prefetch: gumbel tile = 64 rows x 512B = 256 lines; 2 per thread
    {
        const int r = tid & 63, li = tid >> 6;
        const float* gp = gum + (size_t)(bm + r) * VOC + bn + (li << 6);
        pfL2(gp); pfL2(gp + 32);
    }

    const int ka = tid >> 4;                          // 0..7  (rows ka, ka+8)
    const int m4 = (tid & 15) << 2;
    const int kw = tid >> 5;                          // 0..3  (rows kw,+4,+8,+12)
    const int n4 = (tid & 31) << 2;
    const float* srcA = Ht  + (size_t)ka * 512  + bm + m4;
    const float* srcW = OWt + (size_t)kw * 4096 + bn + n4;
    const unsigned dstA = su32(&sm->x3.As[0][ka][m4]);
    const unsigned dstW = su32(&sm->x3.Ws[0][kw][n4]);

    u64 acc[8][4];
#pragma unroll
    for (int i = 0; i < 8; i++)
#pragma unroll
        for (int j = 0; j < 4; j++) acc[i][j] = 0ULL;

    auto issue = [&](int s, int b) {
        const size_t ko = (size_t)s << 4;
        const unsigned bA = (unsigned)b * AS_STRIDE;
        const unsigned bW = (unsigned)b * WS_STRIDE;
        cpa16(dstA + bA,                srcA + ko * 512);
        cpa16(dstA + bA + 8u * AS_ROW,  srcA + (ko + 8) * 512);
        cpa16(dstW + bW,                srcW + ko * 4096);
        cpa16(dstW + bW + 4u * WS_ROW,  srcW + (ko + 4) * 4096);
        cpa16(dstW + bW + 8u * WS_ROW,  srcW + (ko + 8) * 4096);
        cpa16(dstW + bW + 12u * WS_ROW, srcW + (ko + 12) * 4096);
        cpcommit();
    };
    issue(0, 0);
    issue(1, 1);

    for (int s = 0; s < NS; s++) {
        if (s < NS - 1) asm volatile("cp.async.wait_group 1;" ::: "memory");
        else            asm volatile("cp.async.wait_group 0;" ::: "memory");
        __syncthreads();
        if (s + 2 < NS) issue(s + 2, (s + 2) % 3);
        const int cb = s % 3;
#pragma unroll
        for (int k = 0; k < 16; k++) {
            float4 a0 = *(const float4*)&sm->x3.As[cb][k][ty8];
            float4 a1 = *(const float4*)&sm->x3.As[cb][k][ty8 + 4];
            float4 w0 = *(const float4*)&sm->x3.Ws[cb][k][tx8];
            float4 w1 = *(const float4*)&sm->x3.Ws[cb][k][tx8 + 4];
            u64 b0 = pk2(w0.x, w0.y), b1 = pk2(w0.z, w0.w);
            u64 b2 = pk2(w1.x, w1.y), b3 = pk2(w1.z, w1.w);
            u64 A0 = dup2(a0.x), A1 = dup2(a0.y), A2 = dup2(a0.z), A3 = dup2(a0.w);
            u64 A4 = dup2(a1.x), A5 = dup2(a1.y), A6 = dup2(a1.z), A7 = dup2(a1.w);
            acc[0][0]=f2fma(A0,b0,acc[0][0]); acc[0][1]=f2fma(A0,b1,acc[0][1]); acc[0][2]=f2fma(A0,b2,acc[0][2]); acc[0][3]=f2fma(A0,b3,acc[0][3]);
            acc[1][0]=f2fma(A1,b0,acc[1][0]); acc[1][1]=f2fma(A1,b1,acc[1][1]); acc[1][2]=f2fma(A1,b2,acc[1][2]); acc[1][3]=f2fma(A1,b3,acc[1][3]);
            acc[2][0]=f2fma(A2,b0,acc[2][0]); acc[2][1]=f2fma(A2,b1,acc[2][1]); acc[2][2]=f2fma(A2,b2,acc[2][2]); acc[2][3]=f2fma(A2,b3,acc[2][3]);
            acc[3][0]=f2fma(A3,b0,acc[3][0]); acc[3][1]=f2fma(A3,b1,acc[3][1]); acc[3][2]=f2fma(A3,b2,acc[3][2]); acc[3][3]=f2fma(A3,b3,acc[3][3]);
            acc[4][0]=f2fma(A4,b0,acc[4][0]); acc[4][1]=f2fma(A4,b1,acc[4][1]); acc[4][2]=f2fma(A4,b2,acc[4][2]); acc[4][3]=f2fma(A4,b3,acc[4][3]);
            acc[5][0]=f2fma(A5,b0,acc[5][0]); acc[5][1]=f2fma(A5,b1,acc[5][1]); acc[5][2]=f2fma(A5,b2,acc[5][2]); acc[5][3]=f2fma(A5,b3,acc[5][3]);
            acc[6][0]=f2fma(A6,b0,acc[6][0]); acc[6][1]=f2fma(A6,b1,acc[6][1]); acc[6][2]=f2fma(A6,b2,acc[6][2]); acc[6][3]=f2fma(A6,b3,acc[6][3]);
            acc[7][0]=f2fma(A7,b0,acc[7][0]); acc[7][1]=f2fma(A7,b1,acc[7][1]); acc[7][2]=f2fma(A7,b2,acc[7][2]); acc[7][3]=f2fma(A7,b3,acc[7][3]);
        }
    }
    __syncthreads();   // compute done before red union reuse

    float (*s_m)[16] = sm->red.m;
    int   (*s_a)[16] = sm->red.a;
    float* s_rm = sm->red.rm;

    const int row0 = ty8;          // 8 rows per thread
    const int c0 = tx8;

    // pass 1: per-thread max/argmax over 8 cols, per row (z recomputed later)
#pragma unroll
    for (int r = 0; r < 8; r++) {
        const float* gp = gum + (size_t)(bm + row0 + r) * VOC + bn + c0;
        float4 g0 = *(const float4*)&gp[0];
        float4 g1 = *(const float4*)&gp[4];
        float4 o0 = *(const float4*)&ob[bn + c0];
        float4 o1 = *(const float4*)&ob[bn + c0 + 4];
        float2 d0 = up2(acc[r][0]), d1 = up2(acc[r][1]), d2 = up2(acc[r][2]), d3 = up2(acc[r][3]);
        float z0 = d0.x + o0.x + g0.x, z1 = d0.y + o0.y + g0.y;
        float z2 = d1.x + o0.z + g0.z, z3 = d1.y + o0.w + g0.w;
        float z4 = d2.x + o1.x + g1.x, z5 = d2.y + o1.y + g1.y;
        float z6 = d3.x + o1.z + g1.z, z7 = d3.y + o1.w + g1.w;
        float m = z0; int a = bn + c0;
        if (z1 > m) { m = z1; a = bn + c0 + 1; }
        if (z2 > m) { m = z2; a = bn + c0 + 2; }
        if (z3 > m) { m = z3; a = bn + c0 + 3; }
        if (z4 > m) { m = z4; a = bn + c0 + 4; }
        if (z5 > m) { m = z5; a = bn + c0 + 5; }
        if (z6 > m) { m = z6; a = bn + c0 + 6; }
        if (z7 > m) { m = z7; a = bn + c0 + 7; }
        s_m[row0 + r][tx] = m; s_a[row0 + r][tx] = a;
    }
    __syncthreads();
    if (tid < 64) {
        float m = s_m[tid][0]; int a = s_a[tid][0];
#pragma unroll
        for (int x = 1; x < 16; x++)
            if (s_m[tid][x] > m) { m = s_m[tid][x]; a = s_a[tid][x]; }
        s_rm[tid] = m; s_a[tid][0] = a;
    }
    __syncthreads();
    // pass 2: sumexp relative to block-row max
#pragma unroll
    for (int r = 0; r < 8; r++) {
        const float rm = s_rm[row0 + r];
        const float* gp = gum + (size_t)(bm + row0 + r) * VOC + bn + c0;
        float4 g0 = *(const float4*)&gp[0];
        float4 g1 = *(const float4*)&gp[4];
        float4 o0 = *(const float4*)&ob[bn + c0];
        float4 o1 = *(const float4*)&ob[bn + c0 + 4];
        float2 d0 = up2(acc[r][0]), d1 = up2(acc[r][1]), d2 = up2(acc[r][2]), d3 = up2(acc[r][3]);
        float se = __expf(d0.x + o0.x + g0.x - rm);
        se += __expf(d0.y + o0.y + g0.y - rm);
        se += __expf(d1.x + o0.z + g0.z - rm);
        se += __expf(d1.y + o0.w + g0.w - rm);
        se += __expf(d2.x + o1.x + g1.x - rm);
        se += __expf(d2.y + o1.y + g1.y - rm);
        se += __expf(d3.x + o1.z + g1.z - rm);
        se += __expf(d3.y + o1.w + g1.w - rm);
        s_m[row0 + r][tx] = se;
    }
    __syncthreads();
    if (tid < 64) {
        float se = 0.f;
#pragma unroll
        for (int x = 0; x < 16; x++) se += s_m[tid][x];
        const int b = bm + tid;
        g_pm[b * NVT + vt]  = s_rm[tid];
        g_pa[b * NVT + vt]  = s_a[tid][0];
        g_pse[b * NVT + vt] = se;
    }
}

// ---------------- gh tile (cp.async, 8m x 4n per thread), 64x64 -----------
__device__ void gh_tile(int j, const float* __restrict__ Ht,
                        const float* __restrict__ Wt,   // g_Whht [512][1536]
                        const float* __restrict__ bias, SmemU* sm)
{
    const int bm = (j / 24) << 6;
    const int bn = (j % 24) << 6;
    const int tid = threadIdx.x;
    const int tx = tid & 15, ty = tid >> 4;
    const int ty8 = ty << 3;

    const int ka = tid >> 4, m4 = (tid & 15) << 2;
    const float* srcA = Ht + (size_t)ka * 512  + bm + m4;
    const float* srcW = Wt + (size_t)ka * 1536 + bn + m4;
    const unsigned dstA = su32(&sm->x3.As[0][ka][m4]);
    const unsigned dstW = su32(&sm->x3.Ws[0][ka][m4]);

    u64 acc[8][2];
#pragma unroll
    for (int i = 0; i < 8; i++) { acc[i][0] = 0ULL; acc[i][1] = 0ULL; }

    auto issue = [&](int s, int b) {
        const size_t ko = (size_t)s << 4;
        const unsigned bA = (unsigned)b * AS_STRIDE;
        const unsigned bW = (unsigned)b * WS_STRIDE;
        cpa16(dstA + bA,               srcA + ko * 512);
        cpa16(dstA + bA + 8u * AS_ROW, srcA + (ko + 8) * 512);
        cpa16(dstW + bW,               srcW + ko * 1536);
        cpa16(dstW + bW + 8u * WS_ROW, srcW + (ko + 8) * 1536);
        cpcommit();
    };
    issue(0, 0);
    issue(1, 1);

    for (int s = 0; s < NS; s++) {
        if (s < NS - 1) asm volatile("cp.async.wait_group 1;" ::: "memory");
        else            asm volatile("cp.async.wait_group 0;" ::: "memory");
        __syncthreads();
        if (s + 2 < NS) issue(s + 2, (s + 2) % 3);
        const int cb = s % 3;
#pragma unroll
        for (int k = 0; k < 16; k++) {
            float4 a0 = *(const float4*)&sm->x3.As[cb][k][ty8];
            float4 a1 = *(const float4*)&sm->x3.As[cb][k][ty8 + 4];
            float4 w0 = *(const float4*)&sm->x3.Ws[cb][k][tx << 2];
            u64 b0 = pk2(w0.x, w0.y), b1 = pk2(w0.z, w0.w);
            u64 A0 = dup2(a0.x), A1 = dup2(a0.y), A2 = dup2(a0.z), A3 = dup2(a0.w);
            u64 A4 = dup2(a1.x), A5 = dup2(a1.y), A6 = dup2(a1.z), A7 = dup2(a1.w);
            acc[0][0]=f2fma(A0,b0,acc[0][0]); acc[0][1]=f2fma(A0,b1,acc[0][1]);
            acc[1][0]=f2fma(A1,b0,acc[1][0]); acc[1][1]=f2fma(A1,b1,acc[1][1]);
            acc[2][0]=f2fma(A2,b0,acc[2][0]); acc[2][1]=f2fma(A2,b1,acc[2][1]);
            acc[3][0]=f2fma(A3,b0,acc[3][0]); acc[3][1]=f2fma(A3,b1,acc[3][1]);
            acc[4][0]=f2fma(A4,b0,acc[4][0]); acc[4][1]=f2fma(A4,b1,acc[4][1]);
            acc[5][0]=f2fma(A5,b0,acc[5][0]); acc[5][1]=f2fma(A5,b1,acc[5][1]);
            acc[6][0]=f2fma(A6,b0,acc[6][0]); acc[6][1]=f2fma(A6,b1,acc[6][1]);
            acc[7][0]=f2fma(A7,b0,acc[7][0]); acc[7][1]=f2fma(A7,b1,acc[7][1]);
        }
    }
    const int n0 = bn + (tx << 2);
    const float bb0 = bias[n0], bb1 = bias[n0+1], bb2 = bias[n0+2], bb3 = bias[n0+3];
#pragma unroll
    for (int r = 0; r < 8; r++) {
        float2 c0 = up2(acc[r][0]), c1 = up2(acc[r][1]);
        float* cp = g_gh + (size_t)(bm + ty8 + r) * 1536 + n0;
        cp[0] = c0.x + bb0; cp[1] = c0.y + bb1; cp[2] = c1.x + bb2; cp[3] = c1.y + bb3;
    }
}

// ---------------- Y phase: warp-parallel combine + GRU --------------------
__device__ void phase_Y(int t, const float* __restrict__ hin, float* __restrict__ hout,
                        const float* __restrict__ bih, float* __restrict__ lang, SmemU* sm)
{
    const int row0 = blockIdx.x << 1;
    const int tid = threadIdx.x;
    const int wid = tid >> 5, lane = tid & 31;

    if (wid < 2) {
        const int row = row0 + wid;
        int A; float spv;
        if (t > 0) {
            float m = g_pm[row * NVT + lane];
            int   a = g_pa[row * NVT + lane];
            float s = g_pse[row * NVT + lane];
#pragma unroll
            for (int off = 16; off > 0; off >>= 1) {
                const float m2 = __shfl_xor_sync(0xffffffffu, m, off);
                const int   a2 = __shfl_xor_sync(0xffffffffu, a, off);
                const float s2 = __shfl_xor_sync(0xffffffffu, s, off);
                const float M = fmaxf(m, m2);
                s = s * __expf(m - M) + s2 * __expf(m2 - M);
                if (m2 > m || (m2 == m && a2 < a)) a = a2;
                m = M;
            }
            A = a;
            const float si = 1.0f / s;
            spv = (1.0f + si) - si;
            if (lane == 0 && !g_done[row]) {
                lang[(size_t)row * MAXLEN * VOC + (size_t)t * VOC + A] = spv;
                g_len[row] += 1;
                if (A == EOS_IDX) g_done[row] = 1;
            }
        } else { A = SOS_IDX; spv = 1.0f; }
        if (lane == 0) { sm->y.pred[wid] = A; sm->y.sp[wid] = spv; }
    }
    __syncthreads();
    const int p0 = sm->y.pred[0], p1 = sm->y.pred[1];
    const float sp0 = sm->y.sp[0], sp1 = sm->y.sp[1];

#pragma unroll
    for (int j = 0; j < 8; j++) {
        const int idx = j * NT + tid;           // 0..1023
        const int rr_ = idx >> 9;               // 0 or 1
        const int u = idx & 511;
        const int row = row0 + rr_;
        const int p = rr_ ? p1 : p0;
        const float spv = rr_ ? sp1 : sp0;
        const float* ew = g_EW + (size_t)p * 1536;
        const float* gh = g_gh + (size_t)row * 1536;
        const float gir = fmaf(spv, ew[u],        bih[u]);
        const float giz = fmaf(spv, ew[u + 512],  bih[u + 512]);
        const float gin = fmaf(spv, ew[u + 1024], bih[u + 1024]);
        const float r = 1.0f / (1.0f + expf(-(gir + gh[u])));
        const float zz = 1.0f / (1.0f + expf(-(giz + gh[u + 512])));
        const float n = tanhf(gin + r * gh[u + 1024]);
        const float hv = (1.0f - zz) * n + zz * hin[(size_t)row * HID + u];
        hout[(size_t)row * HID + u] = hv;
        g_ht[(size_t)u * 512 + row] = hv;
    }
}

// ---------------- the single persistent kernel -----------------------------
__global__ __launch_bounds__(NT, 3) void speaker_all(
    const float* __restrict__ feats, const int* __restrict__ targets,
    const float* __restrict__ feat_W, const float* __restrict__ feat_b,
    const float* __restrict__ emb_W, const float* __restrict__ init_W,
    const float* __restrict__ init_b, const float* __restrict__ Wih,
    const float* __restrict__ Whh, const float* __restrict__ bih,
    const float* __restrict__ bhh, const float* __restrict__ out_W,
    const float* __restrict__ out_b, const float* __restrict__ gumbel,
    float* __restrict__ out, long long n)
{
    __shared__ SmemU sm;
    const int blk = blockIdx.x;
    const int tid = threadIdx.x;
    float* h0 = g_h[0];
    float* h1 = g_h[1];

    // ---- P0: reset queue; zero output; fe GEMM; EW GEMM; transposes ----
    if (blk == 0 && tid == 0) g_task = 0u;
    {
        const long long n4 = n >> 2;
        float4 zv; zv.x = zv.y = zv.z = zv.w = 0.f;
        for (long long i = (long long)blk * NT + tid; i < n4; i += (long long)NB * NT)
            ((float4*)out)[i] = zv;
        if (blk == 0 && tid < (int)(n & 3)) out[(n & ~3LL) + tid] = 0.f;
    }
    if (blk < 192)   // fe = feats @ feat_W^T + feat_b : [1536, 512]
        gemm64_tile(feats, FEATIN, feat_W, FEATIN, feat_b,
                    g_fe, FEATSZ, FEATIN, (blk >> 3) << 6, (blk & 7) << 6, &sm);
    for (int j = blk; j < 1536; j += NB)   // EW = emb_W @ Wih^T : [4096, 1536]
        gemm64_tile(emb_W, EMB, Wih, EMB, (const float*)0,
                    g_EW, 3 * HID, EMB, (j / 24) << 6, (j % 24) << 6, &sm);
    transpose_tiles(out_W, g_Wot, VOC, HID, &sm);
    transpose_tiles(Whh, g_Whht, 3 * HID, HID, &sm);
    gridbar();

    // ---- P1: build ft; init per-row state + SOS ----
    for (int idx = blk * NT + tid; idx < B_ * FTDIM; idx += NB * NT) {
        const int b = idx / FTDIM, c = idx % FTDIM;
        const int o = c / (FEATSZ + 1), jj = c % (FEATSZ + 1);
        g_ft[idx] = (jj < FEATSZ) ? g_fe[((size_t)b * NOBJ + o) * FEATSZ + jj]
                                  : ((targets[b] == o) ? 1.f : 0.f);
    }
    if (blk < 4) {
        const int b = blk * NT + tid;
        g_done[b] = 0; g_len[b] = 1;
        out[(size_t)b * MAXLEN * VOC + SOS_IDX] = 1.0f;
    }
    gridbar();

    // ---- P2: h0 = ft @ init_W^T + init_b : [512, 512], K=1539 ----
    if (blk < 64)
        gemm64_tile(g_ft, FTDIM, init_W, FTDIM, init_b,
                    h0, HID, FTDIM, (blk >> 3) << 6, (blk & 7) << 6, &sm);
    gridbar();

    // ---- P3: gh(0) = h0 @ Whh^T + bhh ----
    if (blk < 192)
        gemm64_tile(h0, HID, Whh, HID, bhh,
                    g_gh, 3 * HID, HID, (blk / 24) << 6, (blk % 24) << 6, &sm);
    gridbar();

    // ---- main loop ----
    unsigned taskbase = 0u;
    for (int t = 0; t < TSTEPS; t++) {
        const float* hin = (t & 1) ? h1 : h0;
        float* hout      = (t & 1) ? h0 : h1;

        if (blk < 256) phase_Y(t, hin, hout, bih, out, &sm);
        gridbar();

        const int ntasks = (t < TSTEPS - 1) ? (NLOG + NGH) : NLOG;
        const float* gum = gumbel + (size_t)t * B_ * VOC;
        for (;;) {
            __syncthreads();
            if (tid == 0) {
                const unsigned i = atomicAdd(&g_task, 1u);
                sm.task = (int)(i - taskbase);
            }
            __syncthreads();
            const int ti = sm.task;
            if (ti >= ntasks) break;
            if (ti < NLOG) logits_tile(ti, g_ht, g_Wot, out_b, gum, &sm);
            else           gh_tile(ti - NLOG, g_ht, g_Whht, bhh, &sm);
        }
        taskbase += (unsigned)(ntasks + NB);
        gridbar();
    }

    // ---- epilogue: combine(T-1); finalize ----
    if (blk < 256) {
        const int wid = tid >> 5, lane = tid & 31;
        if (wid < 2) {
            const int row = (blk << 1) + wid;
            float m = g_pm[row * NVT + lane];
            int   a = g_pa[row * NVT + lane];
            float s = g_pse[row * NVT + lane];
#pragma unroll
            for (int off = 16; off > 0; off >>= 1) {
                const float m2 = __shfl_xor_sync(0xffffffffu, m, off);
                const int   a2 = __shfl_xor_sync(0xffffffffu, a, off);
                const float s2 = __shfl_xor_sync(0xffffffffu, s, off);
                const float M = fmaxf(m, m2);
                s = s * __expf(m - M) + s2 * __expf(m2 - M);
                if (m2 > m || (m2 == m && a2 < a)) a = a2;
                m = M;
            }
            if (lane == 0) {
                const float si = 1.0f / s;
                const float spv = (1.0f + si) - si;
                int L = g_len[row];
                int done = g_done[row];
                if (!done) {
                    out[(size_t)row * MAXLEN * VOC + (size_t)TSTEPS * VOC + a] = spv;
                    L += 1;
                    if (a == EOS_IDX) done = 1;
                }
                if (!done) {
                    out[(size_t)row * MAXLEN * VOC + (size_t)(MAXLEN - 1) * VOC + EOS_IDX] = 1.0f;
                    L += 1;
                }
                if (LANGN + row < n) out[LANGN + row] = (float)L;
            }
        }
    }
}

// ---------------------------------------------------------------------------
extern "C" void kernel_launch(void* const* d_in, const int* in_sizes, int n_in,
                              void* d_out, int out_size)
{
    const float* feats   = (const float*)d_in[0];
    const int*   targets = (const int*)  d_in[1];
    const float* feat_W  = (const float*)d_in[2];
    const float* feat_b  = (const float*)d_in[3];
    const float* emb_W   = (const float*)d_in[4];
    const float* init_W  = (const float*)d_in[5];
    const float* init_b  = (const float*)d_in[6];
    const float* Wih     = (const float*)d_in[7];
    const float* Whh     = (const float*)d_in[8];
    const float* bih     = (const float*)d_in[9];
    const float* bhh     = (const float*)d_in[10];
    const float* out_W   = (const float*)d_in[11];
    const float* out_b   = (const float*)d_in[12];
    const float* gumbel  = (const float*)d_in[13];

    speaker_all<<<NB, NT>>>(feats, targets, feat_W, feat_b, emb_W, init_W,
                            init_b, Wih, Whh, bih, bhh, out_W, out_b, gumbel,
                            (float*)d_out, (long long)out_size);
}